// round 8
// baseline (speedup 1.0000x reference)
#include <cuda_runtime.h>
#include <cuda_fp16.h>
#include <stdint.h>

namespace {

constexpr int MDIM  = 64;
constexpr int NDIM  = 11008;
constexpr int KDIM  = 4096;
constexpr int NPACK = NDIM / 8;   // 1376
constexpr int BN    = 64;
constexpr int BK    = 64;
constexpr int SK    = 4;          // split-K factor
constexpr int KT_PER = KDIM / BK / SK;  // 16 k-tiles per block

union U32H2 { uint32_t u; __half2 h; };

__device__ __forceinline__ __half2 u2h(uint32_t u) { U32H2 t; t.u = u; return t.h; }
__device__ __forceinline__ uint32_t h2u(__half2 h) { U32H2 t; t.h = h; return t.u; }

__device__ __forceinline__ uint32_t smem_addr(const void* p) {
    return (uint32_t)__cvta_generic_to_shared(p);
}
__device__ __forceinline__ void cp_async16(uint32_t dst, const void* src) {
    asm volatile("cp.async.cg.shared.global [%0], [%1], 16;\n" :: "r"(dst), "l"(src));
}

// fp16 copy of x (inputs arrive as float32 on the wire)
__device__ __align__(16) __half g_x16[MDIM * KDIM];          // 512 KB
// split-K partial sums (deterministic: fixed slot per sk)
__device__ __align__(16) float  g_part[SK * MDIM * NDIM];    // 11.3 MB

__global__ void convert_x_kernel(const float* __restrict__ xf) {
    const int i = blockIdx.x * blockDim.x + threadIdx.x;   // float4 index
    if (i >= MDIM * KDIM / 4) return;
    const float4 v = reinterpret_cast<const float4*>(xf)[i];
    uint2 o;
    o.x = h2u(__floats2half2_rn(v.x, v.y));
    o.y = h2u(__floats2half2_rn(v.z, v.w));
    reinterpret_cast<uint2*>(g_x16)[i] = o;
}

__global__ void reduce_kernel(const float* __restrict__ bias,
                              float* __restrict__ out) {
    const int i = blockIdx.x * blockDim.x + threadIdx.x;   // float4 index
    if (i >= MDIM * NDIM / 4) return;
    const float4* p = reinterpret_cast<const float4*>(g_part);
    constexpr int STRIDE4 = MDIM * NDIM / 4;
    float4 a0 = p[i];
    float4 a1 = p[i + STRIDE4];
    float4 a2 = p[i + 2 * STRIDE4];
    float4 a3 = p[i + 3 * STRIDE4];
    const int col = (i * 4) % NDIM;
    const float4 b = *reinterpret_cast<const float4*>(bias + col);
    float4 r;
    r.x = a0.x + a1.x + a2.x + a3.x + b.x;
    r.y = a0.y + a1.y + a2.y + a3.y + b.y;
    r.z = a0.z + a1.z + a2.z + a3.z + b.z;
    r.w = a0.w + a1.w + a2.w + a3.w + b.w;
    reinterpret_cast<float4*>(out)[i] = r;
}

__device__ __forceinline__ void dequant16(uint32_t v, const __half2* zq2,
                                          const __half2* s2, __half* dst) {
    __half2 w0 = __hmul2(__hsub2(u2h(( v        & 0x000f000fu) | 0x64006400u), zq2[0]), s2[0]);
    __half2 w1 = __hmul2(__hsub2(u2h(((v >> 4)  & 0x000f000fu) | 0x64006400u), zq2[1]), s2[1]);
    __half2 w2 = __hmul2(__hsub2(u2h(((v >> 8)  & 0x000f000fu) | 0x64006400u), zq2[2]), s2[2]);
    __half2 w3 = __hmul2(__hsub2(u2h(((v >> 12) & 0x000f000fu) | 0x64006400u), zq2[3]), s2[3]);
    uint4 pk = make_uint4(h2u(w0), h2u(w1), h2u(w2), h2u(w3));
    *reinterpret_cast<uint4*>(dst) = pk;
}

__global__ __launch_bounds__(256, 3) void awq_gemm_kernel(
    const int*    __restrict__ qw,      // [4096, 1376] int32
    const float*  __restrict__ scales,  // [32, 11008]  f32
    const int*    __restrict__ qzeros)  // [32, 1376]   int32
{
    __shared__ __align__(16) __half xs[3][MDIM * BK];  // 3 x 8KB
    __shared__ __align__(16) __half ws[2][BK * BN];    // 2 x 8KB

    const int tid  = threadIdx.x;
    const int lane = tid & 31;
    const int warp = tid >> 5;
    const int wm   = warp >> 1;         // 0..3  (m tile of 16)
    const int wn   = warp & 1;          // 0..1  (n tile of 32)
    const int nb0  = blockIdx.x * BN;
    const int jb   = blockIdx.x * (BN / 8);
    const int sk   = blockIdx.y;        // 0..3
    const int kt0  = sk * KT_PER;       // first global k-tile (even)

    // dequant work: 512 int32 per tile -> 2 per thread
    const int dq_j = tid & 7;
    const int dq_k = tid >> 3;          // 0..31

    // x tile load: 512 16B chunks -> 2 per thread
    const int xl_m = tid >> 3;          // 0..31
    const int xl_c = tid & 7;           // 0..7

    float acc[4][4] = {};

    __half2 s2[4], zq2[4];
    uint32_t rawz;
    float2   rawf[4];

    // ldmatrix A addressing (x4)
    const int a_row  = wm * 16 + ((lane >> 3) & 1) * 8 + (lane & 7);
    const int a_kgrp = lane >> 4;
    // ldmatrix B addressing (x4.trans)
    const int b_l    = lane & 15;
    const int b_sel  = lane >> 4;

    const __half*  xsrc0 = g_x16 + xl_m * KDIM + xl_c * 8 + kt0 * BK;
    const __half*  xsrc1 = g_x16 + (xl_m + 32) * KDIM + xl_c * 8 + kt0 * BK;
    const uint32_t xoff0 = (uint32_t)(xl_m * BK + ((xl_c ^ (xl_m & 7)) << 3));
    const uint32_t xoff1 = (uint32_t)((xl_m + 32) * BK + ((xl_c ^ (xl_m & 7)) << 3));
    const int*     qcol  = qw + (size_t)kt0 * BK * NPACK + jb + dq_j;
    __half* const  wdst0a = &ws[0][dq_k * BN + ((dq_j ^ (dq_k & 7)) << 3)];
    __half* const  wdst0b = &ws[0][(dq_k + 32) * BN + ((dq_j ^ (dq_k & 7)) << 3)];
    __half* const  wdst1a = &ws[1][dq_k * BN + ((dq_j ^ (dq_k & 7)) << 3)];
    __half* const  wdst1b = &ws[1][(dq_k + 32) * BN + ((dq_j ^ (dq_k & 7)) << 3)];

    // ---- prologue ----
    // group coefficients for tiles 0,1 (group kt0>>1): direct load + convert
    {
        const int g = kt0 >> 1;
        const uint32_t z = (uint32_t)qzeros[g * NPACK + jb + dq_j];
        zq2[0] = u2h(( z         & 0x000f000fu) | 0x64006400u);
        zq2[1] = u2h(((z >> 4)   & 0x000f000fu) | 0x64006400u);
        zq2[2] = u2h(((z >> 8)   & 0x000f000fu) | 0x64006400u);
        zq2[3] = u2h(((z >> 12)  & 0x000f000fu) | 0x64006400u);
        const float2* sp =
            reinterpret_cast<const float2*>(scales + g * NDIM + nb0 + dq_j * 8);
        float2 f0 = sp[0], f1 = sp[1], f2 = sp[2], f3 = sp[3];
        s2[0] = __floats2half2_rn(f0.x, f0.y);
        s2[1] = __floats2half2_rn(f1.x, f1.y);
        s2[2] = __floats2half2_rn(f2.x, f2.y);
        s2[3] = __floats2half2_rn(f3.x, f3.y);
    }
    int qb0 = qcol[dq_k * NPACK];                 // tile 0
    int qb1 = qcol[(dq_k + 32) * NPACK];
    cp_async16(smem_addr(&xs[0][xoff0]), xsrc0);  // x tile 0
    cp_async16(smem_addr(&xs[0][xoff1]), xsrc1);
    asm volatile("cp.async.commit_group;\n");
    int qa0 = qcol[(BK + dq_k) * NPACK];          // tile 1
    int qa1 = qcol[(BK + dq_k + 32) * NPACK];
    cp_async16(smem_addr(&xs[1][xoff0]), xsrc0 + BK);  // x tile 1
    cp_async16(smem_addr(&xs[1][xoff1]), xsrc1 + BK);
    asm volatile("cp.async.commit_group;\n");

    dequant16((uint32_t)qb0, zq2, s2, wdst0a);    // tile 0 -> ws[0]
    dequant16((uint32_t)qb1, zq2, s2, wdst0b);
    qb0 = qa0; qb1 = qa1;
    qa0 = qcol[(2 * BK + dq_k) * NPACK];          // tile 2
    qa1 = qcol[(2 * BK + dq_k + 32) * NPACK];

    asm volatile("cp.async.wait_group 1;\n");     // x tile 0 ready
    __syncthreads();

    for (int t = 0; t < KT_PER; ++t) {
        const int cur  = t & 1;
        const int xcur = t % 3;

        // issue cp.async for x(t+2)
        if (t + 2 < KT_PER) {
            cp_async16(smem_addr(&xs[(t + 2) % 3][xoff0]), xsrc0 + (t + 2) * BK);
            cp_async16(smem_addr(&xs[(t + 2) % 3][xoff1]), xsrc1 + (t + 2) * BK);
            asm volatile("cp.async.commit_group;\n");
        }
        // raw coefficient prefetch for group of tile t+2 (group changes on even t)
        if (((t + 2) & 1) == 0 && t + 2 < KT_PER) {
            const int g = (kt0 + t + 2) >> 1;
            rawz = (uint32_t)qzeros[g * NPACK + jb + dq_j];
            const float2* sp =
                reinterpret_cast<const float2*>(scales + g * NDIM + nb0 + dq_j * 8);
            rawf[0] = sp[0]; rawf[1] = sp[1]; rawf[2] = sp[2]; rawf[3] = sp[3];
        }

        // ---- MMA tile t (xs[xcur], ws[cur]) ----
        #pragma unroll
        for (int kk = 0; kk < 4; ++kk) {
            uint32_t a0, a1, a2, a3;
            {
                const int kc = kk * 2 + a_kgrp;
                const uint32_t addr =
                    smem_addr(&xs[xcur][a_row * BK + ((kc ^ (a_row & 7)) << 3)]);
                asm volatile(
                    "ldmatrix.sync.aligned.m8n8.x4.shared.b16 {%0,%1,%2,%3}, [%4];\n"
                    : "=r"(a0), "=r"(a1), "=r"(a2), "=r"(a3) : "r"(addr));
            }
            #pragma unroll
            for (int p = 0; p < 2; ++p) {
                const int krow  = kk * 16 + b_l;
                const int chunk = wn * 4 + p * 2 + b_sel;
                const uint32_t addr =
                    smem_addr(&ws[cur][krow * BN + ((chunk ^ (krow & 7)) << 3)]);
                uint32_t b0, b1, b2, b3;
                asm volatile(
                    "ldmatrix.sync.aligned.m8n8.x4.trans.shared.b16 {%0,%1,%2,%3}, [%4];\n"
                    : "=r"(b0), "=r"(b1), "=r"(b2), "=r"(b3) : "r"(addr));
                asm volatile(
                    "mma.sync.aligned.m16n8k16.row.col.f32.f16.f16.f32 "
                    "{%0,%1,%2,%3}, {%4,%5,%6,%7}, {%8,%9}, {%0,%1,%2,%3};\n"
                    : "+f"(acc[p*2][0]), "+f"(acc[p*2][1]),
                      "+f"(acc[p*2][2]), "+f"(acc[p*2][3])
                    : "r"(a0), "r"(a1), "r"(a2), "r"(a3), "r"(b0), "r"(b1));
                asm volatile(
                    "mma.sync.aligned.m16n8k16.row.col.f32.f16.f16.f32 "
                    "{%0,%1,%2,%3}, {%4,%5,%6,%7}, {%8,%9}, {%0,%1,%2,%3};\n"
                    : "+f"(acc[p*2+1][0]), "+f"(acc[p*2+1][1]),
                      "+f"(acc[p*2+1][2]), "+f"(acc[p*2+1][3])
                    : "r"(a0), "r"(a1), "r"(a2), "r"(a3), "r"(b2), "r"(b3));
            }
        }

        // ---- dequant tile t+1 into the other ws buffer (overlaps MMA latency) ----
        if (t + 1 < KT_PER) {
            if (((kt0 + t + 1) & 1) == 0) {   // tile t+1 starts a new group
                zq2[0] = u2h(( rawz         & 0x000f000fu) | 0x64006400u);
                zq2[1] = u2h(((rawz >> 4)   & 0x000f000fu) | 0x64006400u);
                zq2[2] = u2h(((rawz >> 8)   & 0x000f000fu) | 0x64006400u);
                zq2[3] = u2h(((rawz >> 12)  & 0x000f000fu) | 0x64006400u);
                s2[0] = __floats2half2_rn(rawf[0].x, rawf[0].y);
                s2[1] = __floats2half2_rn(rawf[1].x, rawf[1].y);
                s2[2] = __floats2half2_rn(rawf[2].x, rawf[2].y);
                s2[3] = __floats2half2_rn(rawf[3].x, rawf[3].y);
            }
            dequant16((uint32_t)qb0, zq2, s2, cur ? wdst0a : wdst1a);
            dequant16((uint32_t)qb1, zq2, s2, cur ? wdst0b : wdst1b);
            qb0 = qa0; qb1 = qa1;
            if (t + 3 < KT_PER) {
                qa0 = qcol[((t + 3) * BK + dq_k) * NPACK];
                qa1 = qcol[((t + 3) * BK + dq_k + 32) * NPACK];
            }

            if (t + 2 < KT_PER) { asm volatile("cp.async.wait_group 1;\n"); }
            else                { asm volatile("cp.async.wait_group 0;\n"); }
            __syncthreads();
        }
    }

    // ---- epilogue: store fp32 partials (bias added in reduce) ----
    float* part = g_part + (size_t)sk * MDIM * NDIM;
    const int r   = lane >> 2;
    const int cpr = (lane & 3) * 2;
    #pragma unroll
    for (int cn = 0; cn < 4; ++cn) {
        const int col  = nb0 + wn * 32 + cn * 8 + cpr;
        const int row0 = wm * 16 + r;
        *reinterpret_cast<float2*>(part + row0 * NDIM + col) =
            make_float2(acc[cn][0], acc[cn][1]);
        *reinterpret_cast<float2*>(part + (row0 + 8) * NDIM + col) =
            make_float2(acc[cn][2], acc[cn][3]);
    }
}

} // namespace

extern "C" void kernel_launch(void* const* d_in, const int* in_sizes, int n_in,
                              void* d_out, int out_size) {
    const float* x       = (const float*)d_in[0];
    const int*   qweight = (const int*)  d_in[1];
    const float* scales  = (const float*)d_in[2];
    const int*   qzeros  = (const int*)  d_in[3];
    const float* bias    = (const float*)d_in[4];
    float*       out     = (float*)d_out;

    convert_x_kernel<<<(MDIM * KDIM / 4 + 255) / 256, 256>>>(x);

    dim3 grid(NDIM / BN, SK);   // 172 x 4 = 688 blocks
    awq_gemm_kernel<<<grid, 256>>>(qweight, scales, qzeros);

    reduce_kernel<<<(MDIM * NDIM / 4 + 255) / 256, 256>>>(bias, out);
}

// round 9
// speedup vs baseline: 1.2721x; 1.2721x over previous
#include <cuda_runtime.h>
#include <cuda_fp16.h>
#include <stdint.h>

namespace {

constexpr int MDIM  = 64;
constexpr int NDIM  = 11008;
constexpr int KDIM  = 4096;
constexpr int NPACK = NDIM / 8;   // 1376
constexpr int BN    = 64;
constexpr int BK    = 64;
constexpr int SK    = 4;          // split-K factor
constexpr int KT_PER = KDIM / BK / SK;  // 16 k-tiles per block

union U32H2 { uint32_t u; __half2 h; };

__device__ __forceinline__ __half2 u2h(uint32_t u) { U32H2 t; t.u = u; return t.h; }
__device__ __forceinline__ uint32_t h2u(__half2 h) { U32H2 t; t.h = h; return t.u; }

__device__ __forceinline__ uint32_t smem_addr(const void* p) {
    return (uint32_t)__cvta_generic_to_shared(p);
}
__device__ __forceinline__ void cp_async16(uint32_t dst, const void* src) {
    asm volatile("cp.async.cg.shared.global [%0], [%1], 16;\n" :: "r"(dst), "l"(src));
}

// fp16 copy of x (inputs arrive as float32 on the wire)
__device__ __align__(16) __half g_x16[MDIM * KDIM];          // 512 KB
// split-K partial sums (deterministic: fixed slot per sk)
__device__ __align__(16) float  g_part[SK * MDIM * NDIM];    // 11.3 MB

// ILP=4 convert: 64 blocks x 256 threads x 4 float4 = 65536 float4 (exact)
__global__ void convert_x_kernel(const float* __restrict__ xf) {
    const int base = blockIdx.x * 1024 + threadIdx.x;
    const float4* src = reinterpret_cast<const float4*>(xf);
    uint2* dst = reinterpret_cast<uint2*>(g_x16);
    #pragma unroll
    for (int j = 0; j < 4; ++j) {
        const int i = base + j * 256;
        const float4 v = src[i];
        uint2 o;
        o.x = h2u(__floats2half2_rn(v.x, v.y));
        o.y = h2u(__floats2half2_rn(v.z, v.w));
        dst[i] = o;
    }
}

// ILP=2 reduce: 344 blocks x 256 threads x 2 float4 = 176128 float4 (exact)
__global__ void reduce_kernel(const float* __restrict__ bias,
                              float* __restrict__ out) {
    const int base = blockIdx.x * 512 + threadIdx.x;
    const float4* p = reinterpret_cast<const float4*>(g_part);
    constexpr int STRIDE4 = MDIM * NDIM / 4;
    #pragma unroll
    for (int j = 0; j < 2; ++j) {
        const int i = base + j * 256;
        float4 a0 = p[i];
        float4 a1 = p[i + STRIDE4];
        float4 a2 = p[i + 2 * STRIDE4];
        float4 a3 = p[i + 3 * STRIDE4];
        const int col = (i * 4) % NDIM;
        const float4 b = *reinterpret_cast<const float4*>(bias + col);
        float4 r;
        r.x = a0.x + a1.x + a2.x + a3.x + b.x;
        r.y = a0.y + a1.y + a2.y + a3.y + b.y;
        r.z = a0.z + a1.z + a2.z + a3.z + b.z;
        r.w = a0.w + a1.w + a2.w + a3.w + b.w;
        reinterpret_cast<float4*>(out)[i] = r;
    }
}

__device__ __forceinline__ void dequant16(uint32_t v, const __half2* zq2,
                                          const __half2* s2, __half* dst) {
    __half2 w0 = __hmul2(__hsub2(u2h(( v        & 0x000f000fu) | 0x64006400u), zq2[0]), s2[0]);
    __half2 w1 = __hmul2(__hsub2(u2h(((v >> 4)  & 0x000f000fu) | 0x64006400u), zq2[1]), s2[1]);
    __half2 w2 = __hmul2(__hsub2(u2h(((v >> 8)  & 0x000f000fu) | 0x64006400u), zq2[2]), s2[2]);
    __half2 w3 = __hmul2(__hsub2(u2h(((v >> 12) & 0x000f000fu) | 0x64006400u), zq2[3]), s2[3]);
    uint4 pk = make_uint4(h2u(w0), h2u(w1), h2u(w2), h2u(w3));
    *reinterpret_cast<uint4*>(dst) = pk;
}

__global__ __launch_bounds__(128, 5) void awq_gemm_kernel(
    const int*    __restrict__ qw,      // [4096, 1376] int32
    const float*  __restrict__ scales,  // [32, 11008]  f32
    const int*    __restrict__ qzeros)  // [32, 1376]   int32
{
    __shared__ __align__(16) __half xs[2][MDIM * BK];  // 2 x 8KB
    __shared__ __align__(16) __half ws[2][BK * BN];    // 2 x 8KB

    const int tid  = threadIdx.x;
    const int lane = tid & 31;
    const int warp = tid >> 5;          // 0..3
    const int wm   = warp & 1;          // m half of 32 rows
    const int wn   = warp >> 1;         // n half of 32 cols
    const int nb0  = blockIdx.x * BN;
    const int jb   = blockIdx.x * (BN / 8);
    const int sk   = blockIdx.y;        // 0..3
    const int kt0  = sk * KT_PER;       // first global k-tile

    // dequant: 512 int32 per tile -> 4 per thread (rows dq_k + 16r)
    const int dq_j = tid & 7;
    const int dq_k = tid >> 3;          // 0..15
    // x tile load: 512 16B chunks -> 4 per thread (rows xl_m + 16r)
    const int xl_m = tid >> 3;          // 0..15
    const int xl_c = tid & 7;           // 0..7

    float acc[4][2][4] = {};            // [n8 chunk][m frag][regs]

    __half2 s2[4], zq2[4];
    int cur_g = -1;

    // ldmatrix A addressing (x4, per 16-row m-frag)
    const int a_row  = wm * 32 + ((lane >> 3) & 1) * 8 + (lane & 7);
    const int a_kgrp = lane >> 4;
    // ldmatrix B addressing (x4.trans) — identical to validated R6 path
    const int b_l    = lane & 15;
    const int b_sel  = lane >> 4;

    const __half* xsrc[4];
    uint32_t      xoff[4];
    #pragma unroll
    for (int r = 0; r < 4; ++r) {
        const int row = xl_m + 16 * r;
        xsrc[r] = g_x16 + row * KDIM + xl_c * 8 + kt0 * BK;
        xoff[r] = (uint32_t)(row * BK + ((xl_c ^ (row & 7)) << 3));  // (row&7)==(xl_m&7)
    }
    const int* qcol = qw + (size_t)kt0 * BK * NPACK + jb + dq_j;
    const uint32_t wsw = (uint32_t)((dq_j ^ (dq_k & 7)) << 3);       // same for all 4 rows

    // ---- prologue: stage tile 0 ----
    #pragma unroll
    for (int r = 0; r < 4; ++r) cp_async16(smem_addr(&xs[0][xoff[r]]), xsrc[r]);
    asm volatile("cp.async.commit_group;\n");
    int q[4];
    #pragma unroll
    for (int r = 0; r < 4; ++r) q[r] = qcol[(dq_k + 16 * r) * NPACK];

    for (int t = 0; t < KT_PER; ++t) {
        const int cur = t & 1;

        // per-group coefficients (group changes every 2 tiles)
        const int g = (kt0 + t) >> 1;
        if (g != cur_g) {
            cur_g = g;
            const uint32_t z = (uint32_t)qzeros[g * NPACK + jb + dq_j];
            zq2[0] = u2h(( z         & 0x000f000fu) | 0x64006400u);
            zq2[1] = u2h(((z >> 4)   & 0x000f000fu) | 0x64006400u);
            zq2[2] = u2h(((z >> 8)   & 0x000f000fu) | 0x64006400u);
            zq2[3] = u2h(((z >> 12)  & 0x000f000fu) | 0x64006400u);
            const float2* sp =
                reinterpret_cast<const float2*>(scales + g * NDIM + nb0 + dq_j * 8);
            float2 f0 = sp[0], f1 = sp[1], f2 = sp[2], f3 = sp[3];
            s2[0] = __floats2half2_rn(f0.x, f0.y);
            s2[1] = __floats2half2_rn(f1.x, f1.y);
            s2[2] = __floats2half2_rn(f2.x, f2.y);
            s2[3] = __floats2half2_rn(f3.x, f3.y);
        }

        // ---- dequant 4 int32s -> 32 fp16 weights -> swizzled smem ----
        #pragma unroll
        for (int r = 0; r < 4; ++r) {
            dequant16((uint32_t)q[r], zq2, s2,
                      &ws[cur][(dq_k + 16 * r) * BN + wsw]);
        }

        asm volatile("cp.async.wait_group 0;\n");
        __syncthreads();

        // ---- prefetch next tile (overlaps with MMA below) ----
        if (t + 1 < KT_PER) {
            const int k1 = (t + 1) * BK;
            #pragma unroll
            for (int r = 0; r < 4; ++r)
                cp_async16(smem_addr(&xs[cur ^ 1][xoff[r]]), xsrc[r] + k1);
            asm volatile("cp.async.commit_group;\n");
            #pragma unroll
            for (int r = 0; r < 4; ++r)
                q[r] = qcol[(k1 + dq_k + 16 * r) * NPACK];
        }

        // ---- MMA over 4 k16 sub-steps, warp tile m32 x n32 ----
        #pragma unroll
        for (int kk = 0; kk < 4; ++kk) {
            uint32_t a[2][4];
            #pragma unroll
            for (int mf = 0; mf < 2; ++mf) {
                const int row = a_row + mf * 16;     // (row&7) == (a_row&7)
                const int kc  = kk * 2 + a_kgrp;
                const uint32_t addr =
                    smem_addr(&xs[cur][row * BK + ((kc ^ (row & 7)) << 3)]);
                asm volatile(
                    "ldmatrix.sync.aligned.m8n8.x4.shared.b16 {%0,%1,%2,%3}, [%4];\n"
                    : "=r"(a[mf][0]), "=r"(a[mf][1]), "=r"(a[mf][2]), "=r"(a[mf][3])
                    : "r"(addr));
            }
            #pragma unroll
            for (int p = 0; p < 2; ++p) {
                const int krow  = kk * 16 + b_l;
                const int chunk = wn * 4 + p * 2 + b_sel;
                const uint32_t addr =
                    smem_addr(&ws[cur][krow * BN + ((chunk ^ (krow & 7)) << 3)]);
                uint32_t b0, b1, b2, b3;
                asm volatile(
                    "ldmatrix.sync.aligned.m8n8.x4.trans.shared.b16 {%0,%1,%2,%3}, [%4];\n"
                    : "=r"(b0), "=r"(b1), "=r"(b2), "=r"(b3) : "r"(addr));
                #pragma unroll
                for (int mf = 0; mf < 2; ++mf) {
                    asm volatile(
                        "mma.sync.aligned.m16n8k16.row.col.f32.f16.f16.f32 "
                        "{%0,%1,%2,%3}, {%4,%5,%6,%7}, {%8,%9}, {%0,%1,%2,%3};\n"
                        : "+f"(acc[p*2][mf][0]), "+f"(acc[p*2][mf][1]),
                          "+f"(acc[p*2][mf][2]), "+f"(acc[p*2][mf][3])
                        : "r"(a[mf][0]), "r"(a[mf][1]), "r"(a[mf][2]), "r"(a[mf][3]),
                          "r"(b0), "r"(b1));
                    asm volatile(
                        "mma.sync.aligned.m16n8k16.row.col.f32.f16.f16.f32 "
                        "{%0,%1,%2,%3}, {%4,%5,%6,%7}, {%8,%9}, {%0,%1,%2,%3};\n"
                        : "+f"(acc[p*2+1][mf][0]), "+f"(acc[p*2+1][mf][1]),
                          "+f"(acc[p*2+1][mf][2]), "+f"(acc[p*2+1][mf][3])
                        : "r"(a[mf][0]), "r"(a[mf][1]), "r"(a[mf][2]), "r"(a[mf][3]),
                          "r"(b2), "r"(b3));
                }
            }
        }
    }

    // ---- epilogue: store fp32 partials (bias added in reduce) ----
    float* part = g_part + (size_t)sk * MDIM * NDIM;
    const int r   = lane >> 2;
    const int cpr = (lane & 3) * 2;
    #pragma unroll
    for (int cn = 0; cn < 4; ++cn) {
        const int col = nb0 + wn * 32 + cn * 8 + cpr;
        #pragma unroll
        for (int mf = 0; mf < 2; ++mf) {
            const int row0 = wm * 32 + mf * 16 + r;
            *reinterpret_cast<float2*>(part + row0 * NDIM + col) =
                make_float2(acc[cn][mf][0], acc[cn][mf][1]);
            *reinterpret_cast<float2*>(part + (row0 + 8) * NDIM + col) =
                make_float2(acc[cn][mf][2], acc[cn][mf][3]);
        }
    }
}

} // namespace

extern "C" void kernel_launch(void* const* d_in, const int* in_sizes, int n_in,
                              void* d_out, int out_size) {
    const float* x       = (const float*)d_in[0];
    const int*   qweight = (const int*)  d_in[1];
    const float* scales  = (const float*)d_in[2];
    const int*   qzeros  = (const int*)  d_in[3];
    const float* bias    = (const float*)d_in[4];
    float*       out     = (float*)d_out;

    convert_x_kernel<<<64, 256>>>(x);

    dim3 grid(NDIM / BN, SK);   // 172 x 4 = 688 blocks
    awq_gemm_kernel<<<grid, 128>>>(qweight, scales, qzeros);

    reduce_kernel<<<344, 256>>>(bias, out);
}